// round 2
// baseline (speedup 1.0000x reference)
#include <cuda_runtime.h>

// out = (idx[...,0] >= 0) ? shaded[idx0] : (1,1,1)
// (binary-weight alpha composite selects the first valid fragment; bg_mask on
//  slot 0 then overrides everything else — only fragment layer 0 matters)

#define MAX_P 131072
#define PX_PER_THREAD 8

__device__ float4 g_shaded[MAX_P];  // rgb + pad for 16B-aligned gathers

__global__ void shade_kernel(const float* __restrict__ features,
                             const float* __restrict__ normals,
                             const float* __restrict__ light_dir,
                             int P) {
    int i = blockIdx.x * blockDim.x + threadIdx.x;
    if (i >= P) return;

    float lx = light_dir[0], ly = light_dir[1], lz = light_dir[2];
    float inv = rsqrtf(lx * lx + ly * ly + lz * lz);
    lx *= inv; ly *= inv; lz *= inv;

    float nx = normals[3 * i + 0];
    float ny = normals[3 * i + 1];
    float nz = normals[3 * i + 2];
    float ndl = fabsf(nx * lx + ny * ly + nz * lz);
    float s = 0.6f + 0.8f * ndl;  // AMBIENT + DIFFUSE * |n.l|

    float r = fminf(fmaxf(features[3 * i + 0] * s, 0.0f), 1.0f);
    float g = fminf(fmaxf(features[3 * i + 1] * s, 0.0f), 1.0f);
    float b = fminf(fmaxf(features[3 * i + 2] * s, 0.0f), 1.0f);
    g_shaded[i] = make_float4(r, g, b, 0.0f);
}

// 8 pixels/thread, explicit two-phase MLP:
//   phase 1: 8 independent strided idx LDGs in flight
//   phase 2: 8 independent float4 table gathers in flight
//   phase 3: 6 coalesced STG.128
__global__ __launch_bounds__(256) void composite_kernel(
        const int* __restrict__ idx,
        float4* __restrict__ out4,
        int n_pix, int K) {
    const float4* __restrict__ tab = g_shaded;
    long t = (long)blockIdx.x * blockDim.x + threadIdx.x;
    long p0 = t * PX_PER_THREAD;
    if (p0 >= n_pix) return;

    bool full = (p0 + PX_PER_THREAD) <= n_pix;

    int ids[PX_PER_THREAD];
#pragma unroll
    for (int j = 0; j < PX_PER_THREAD; j++) {
        long p = p0 + j;
        ids[j] = (full || p < n_pix) ? __ldg(&idx[p * (long)K]) : -1;
    }

    float4 v[PX_PER_THREAD];
#pragma unroll
    for (int j = 0; j < PX_PER_THREAD; j++) {
        v[j] = (ids[j] >= 0) ? __ldg(&tab[ids[j]])
                             : make_float4(1.0f, 1.0f, 1.0f, 0.0f);
    }

    float c[3 * PX_PER_THREAD];
#pragma unroll
    for (int j = 0; j < PX_PER_THREAD; j++) {
        c[3 * j + 0] = v[j].x;
        c[3 * j + 1] = v[j].y;
        c[3 * j + 2] = v[j].z;
    }

    if (full) {
        float4* o = out4 + t * 6;
#pragma unroll
        for (int i = 0; i < 6; i++)
            o[i] = make_float4(c[4 * i + 0], c[4 * i + 1],
                               c[4 * i + 2], c[4 * i + 3]);
    } else {
        float* of = (float*)out4 + p0 * 3;
        long nf = (n_pix - p0) * 3;
        for (long i = 0; i < nf; i++) of[i] = c[i];
    }
}

extern "C" void kernel_launch(void* const* d_in, const int* in_sizes, int n_in,
                              void* d_out, int out_size) {
    const int*   idx       = (const int*)d_in[0];
    const float* features  = (const float*)d_in[1];
    const float* normals   = (const float*)d_in[2];
    const float* light_dir = (const float*)d_in[3];

    int n_pix = out_size / 3;                 // N*H*W
    int K     = in_sizes[0] / n_pix;          // fragments per pixel (10)
    int P     = in_sizes[1] / 3;              // number of points (100000)
    if (P > MAX_P) P = MAX_P;

    {
        int threads = 256;
        int blocks = (P + threads - 1) / threads;
        shade_kernel<<<blocks, threads>>>(features, normals, light_dir, P);
    }
    {
        int threads = 256;
        long n_thr = ((long)n_pix + PX_PER_THREAD - 1) / PX_PER_THREAD;
        int blocks = (int)((n_thr + threads - 1) / threads);
        composite_kernel<<<blocks, threads>>>(idx, (float4*)d_out, n_pix, K);
    }
}

// round 3
// speedup vs baseline: 1.0396x; 1.0396x over previous
#include <cuda_runtime.h>
#include <cuda_fp16.h>

// out = (idx[...,0] >= 0) ? shaded[idx0] : (1,1,1)
// (binary-weight alpha composite keeps only the first fragment; bg_mask on
//  slot 0 overrides the rest — only idx[...,0] matters)

#define MAX_P 131072
#define PX_PER_THREAD 8

// fp16 rgb packed into 8B: .x = half2(r,g), .y = half2(b,0)
__device__ uint2 g_tab[MAX_P];

__global__ void shade_kernel(const float* __restrict__ features,
                             const float* __restrict__ normals,
                             const float* __restrict__ light_dir,
                             int P) {
    int i = blockIdx.x * blockDim.x + threadIdx.x;
    if (i >= P) return;

    float lx = light_dir[0], ly = light_dir[1], lz = light_dir[2];
    float inv = rsqrtf(lx * lx + ly * ly + lz * lz);
    lx *= inv; ly *= inv; lz *= inv;

    float nx = normals[3 * i + 0];
    float ny = normals[3 * i + 1];
    float nz = normals[3 * i + 2];
    float ndl = fabsf(nx * lx + ny * ly + nz * lz);
    float s = 0.6f + 0.8f * ndl;  // AMBIENT + DIFFUSE * |n.l|

    float r = fminf(fmaxf(features[3 * i + 0] * s, 0.0f), 1.0f);
    float g = fminf(fmaxf(features[3 * i + 1] * s, 0.0f), 1.0f);
    float b = fminf(fmaxf(features[3 * i + 2] * s, 0.0f), 1.0f);

    __half2 rg = __floats2half2_rn(r, g);
    __half2 b0 = __floats2half2_rn(b, 0.0f);
    uint2 packed;
    packed.x = *(unsigned int*)&rg;
    packed.y = *(unsigned int*)&b0;
    g_tab[i] = packed;
}

// 8 pixels/thread, two-phase MLP:
//   phase 1: 8 independent strided idx LDGs
//   phase 2: 8 independent 8B table gathers
//   phase 3: 6 coalesced STG.128
__global__ __launch_bounds__(256, 6) void composite_kernel(
        const int* __restrict__ idx,
        float4* __restrict__ out4,
        int n_pix, int K) {
    const uint2* __restrict__ tab = g_tab;
    long t = (long)blockIdx.x * blockDim.x + threadIdx.x;
    long p0 = t * PX_PER_THREAD;
    if (p0 >= n_pix) return;

    bool full = (p0 + PX_PER_THREAD) <= n_pix;

    int ids[PX_PER_THREAD];
#pragma unroll
    for (int j = 0; j < PX_PER_THREAD; j++) {
        long p = p0 + j;
        ids[j] = (full || p < n_pix) ? __ldg(&idx[p * (long)K]) : -1;
    }

    // white in packed-fp16 form: half2(1,1), half2(1,0)
    const unsigned int ONE2 = 0x3C003C00u;
    const unsigned int ONE0 = 0x00003C00u;

    uint2 v[PX_PER_THREAD];
#pragma unroll
    for (int j = 0; j < PX_PER_THREAD; j++) {
        v[j] = (ids[j] >= 0) ? __ldg(&tab[ids[j]]) : make_uint2(ONE2, ONE0);
    }

    float c[3 * PX_PER_THREAD];
#pragma unroll
    for (int j = 0; j < PX_PER_THREAD; j++) {
        float2 rg = __half22float2(*(__half2*)&v[j].x);
        float2 b0 = __half22float2(*(__half2*)&v[j].y);
        c[3 * j + 0] = rg.x;
        c[3 * j + 1] = rg.y;
        c[3 * j + 2] = b0.x;
    }

    if (full) {
        float4* o = out4 + t * 6;
#pragma unroll
        for (int i = 0; i < 6; i++)
            o[i] = make_float4(c[4 * i + 0], c[4 * i + 1],
                               c[4 * i + 2], c[4 * i + 3]);
    } else {
        float* of = (float*)out4 + p0 * 3;
        long nf = (n_pix - p0) * 3;
        for (long i = 0; i < nf; i++) of[i] = c[i];
    }
}

extern "C" void kernel_launch(void* const* d_in, const int* in_sizes, int n_in,
                              void* d_out, int out_size) {
    const int*   idx       = (const int*)d_in[0];
    const float* features  = (const float*)d_in[1];
    const float* normals   = (const float*)d_in[2];
    const float* light_dir = (const float*)d_in[3];

    int n_pix = out_size / 3;                 // N*H*W
    int K     = in_sizes[0] / n_pix;          // fragments per pixel (10)
    int P     = in_sizes[1] / 3;              // number of points (100000)
    if (P > MAX_P) P = MAX_P;

    {
        int threads = 256;
        int blocks = (P + threads - 1) / threads;
        shade_kernel<<<blocks, threads>>>(features, normals, light_dir, P);
    }
    {
        int threads = 256;
        long n_thr = ((long)n_pix + PX_PER_THREAD - 1) / PX_PER_THREAD;
        int blocks = (int)((n_thr + threads - 1) / threads);
        composite_kernel<<<blocks, threads>>>(idx, (float4*)d_out, n_pix, K);
    }
}

// round 4
// speedup vs baseline: 1.0837x; 1.0425x over previous
#include <cuda_runtime.h>
#include <cuda_fp16.h>

// out = (idx[...,0] >= 0) ? shaded[idx0] : (1,1,1)
// (binary-weight alpha composite keeps only the first fragment; bg_mask on
//  slot 0 overrides the rest — only idx[...,0] matters)

#define MAX_P 131072
#define PX_PER_THREAD 4

// fp16 rgb packed into 8B: .x = half2(r,g), .y = half2(b,_)
__device__ uint2 g_tab[MAX_P];

__global__ void shade_kernel(const float* __restrict__ features,
                             const float* __restrict__ normals,
                             const float* __restrict__ light_dir,
                             int P) {
    int i = blockIdx.x * blockDim.x + threadIdx.x;
    if (i >= P) return;

    float lx = light_dir[0], ly = light_dir[1], lz = light_dir[2];
    float inv = rsqrtf(lx * lx + ly * ly + lz * lz);
    lx *= inv; ly *= inv; lz *= inv;

    float nx = normals[3 * i + 0];
    float ny = normals[3 * i + 1];
    float nz = normals[3 * i + 2];
    float ndl = fabsf(nx * lx + ny * ly + nz * lz);
    float s = 0.6f + 0.8f * ndl;  // AMBIENT + DIFFUSE * |n.l|

    float r = fminf(fmaxf(features[3 * i + 0] * s, 0.0f), 1.0f);
    float g = fminf(fmaxf(features[3 * i + 1] * s, 0.0f), 1.0f);
    float b = fminf(fmaxf(features[3 * i + 2] * s, 0.0f), 1.0f);

    __half2 rg = __floats2half2_rn(r, g);
    __half2 b0 = __floats2half2_rn(b, 0.0f);
    uint2 packed;
    packed.x = *(unsigned int*)&rg;
    packed.y = *(unsigned int*)&b0;
    g_tab[i] = packed;
}

// Warp-interleaved layout: lane l, iter j -> pixel warp_base + 32*j + l.
// idx LDG per warp covers 32 consecutive pixels (40B stride -> 10 lines,
// 10 wavefronts instead of 32). Two-phase MLP=4.
__global__ __launch_bounds__(256) void composite_kernel(
        const int* __restrict__ idx,
        float* __restrict__ out,
        int n_pix, int K) {
    const uint2* __restrict__ tab = g_tab;

    long warp_global = ((long)blockIdx.x * blockDim.x + threadIdx.x) >> 5;
    int lane = threadIdx.x & 31;
    long base = warp_global * (32 * PX_PER_THREAD) + lane;

    int ids[PX_PER_THREAD];
#pragma unroll
    for (int j = 0; j < PX_PER_THREAD; j++) {
        long p = base + 32 * j;
        ids[j] = (p < n_pix) ? __ldg(&idx[p * (long)K]) : -1;
    }

    // white in packed-fp16 form: half2(1,1), half2(1,0)
    const unsigned int ONE2 = 0x3C003C00u;
    const unsigned int ONE0 = 0x00003C00u;

    uint2 v[PX_PER_THREAD];
#pragma unroll
    for (int j = 0; j < PX_PER_THREAD; j++) {
        v[j] = (ids[j] >= 0) ? __ldg(&tab[ids[j]]) : make_uint2(ONE2, ONE0);
    }

#pragma unroll
    for (int j = 0; j < PX_PER_THREAD; j++) {
        long p = base + 32 * j;
        if (p < n_pix) {
            float2 rg = __half22float2(*(__half2*)&v[j].x);
            float2 b0 = __half22float2(*(__half2*)&v[j].y);
            out[p * 3 + 0] = rg.x;
            out[p * 3 + 1] = rg.y;
            out[p * 3 + 2] = b0.x;
        }
    }
}

extern "C" void kernel_launch(void* const* d_in, const int* in_sizes, int n_in,
                              void* d_out, int out_size) {
    const int*   idx       = (const int*)d_in[0];
    const float* features  = (const float*)d_in[1];
    const float* normals   = (const float*)d_in[2];
    const float* light_dir = (const float*)d_in[3];

    int n_pix = out_size / 3;                 // N*H*W
    int K     = in_sizes[0] / n_pix;          // fragments per pixel (10)
    int P     = in_sizes[1] / 3;              // number of points (100000)
    if (P > MAX_P) P = MAX_P;

    {
        int threads = 256;
        int blocks = (P + threads - 1) / threads;
        shade_kernel<<<blocks, threads>>>(features, normals, light_dir, P);
    }
    {
        int threads = 256;
        long px_per_block = (long)threads * PX_PER_THREAD;
        int blocks = (int)((n_pix + px_per_block - 1) / px_per_block);
        composite_kernel<<<blocks, threads>>>(idx, (float*)d_out, n_pix, K);
    }
}

// round 5
// speedup vs baseline: 1.1737x; 1.0830x over previous
#include <cuda_runtime.h>
#include <cuda_fp16.h>

// out = (idx[...,0] >= 0) ? shaded[idx0] : (1,1,1)
// (binary-weight alpha composite keeps only the first fragment; bg_mask on
//  slot 0 overrides the rest — only idx[...,0] matters)

#define MAX_P 131072
#define PX_PER_THREAD 8

// fp16 rgb packed into 8B: .x = half2(r,g), .y = half2(b,_)
__device__ uint2 g_tab[MAX_P];

__global__ void shade_kernel(const float* __restrict__ features,
                             const float* __restrict__ normals,
                             const float* __restrict__ light_dir,
                             int P) {
    int i = blockIdx.x * blockDim.x + threadIdx.x;
    if (i >= P) return;

    float lx = light_dir[0], ly = light_dir[1], lz = light_dir[2];
    float inv = rsqrtf(lx * lx + ly * ly + lz * lz);
    lx *= inv; ly *= inv; lz *= inv;

    float nx = normals[3 * i + 0];
    float ny = normals[3 * i + 1];
    float nz = normals[3 * i + 2];
    float ndl = fabsf(nx * lx + ny * ly + nz * lz);
    float s = 0.6f + 0.8f * ndl;  // AMBIENT + DIFFUSE * |n.l|

    float r = fminf(fmaxf(features[3 * i + 0] * s, 0.0f), 1.0f);
    float g = fminf(fmaxf(features[3 * i + 1] * s, 0.0f), 1.0f);
    float b = fminf(fmaxf(features[3 * i + 2] * s, 0.0f), 1.0f);

    __half2 rg = __floats2half2_rn(r, g);
    __half2 b0 = __floats2half2_rn(b, 0.0f);
    uint2 packed;
    packed.x = *(unsigned int*)&rg;
    packed.y = *(unsigned int*)&b0;
    g_tab[i] = packed;
}

// Warp-interleaved layout: lane l, iter j -> pixel warp_base + 32*j + l.
// Per warp-iter the idx LDG covers 32 consecutive pixels (40B stride -> 10
// L1 lines). Two-phase MLP=8: 8 independent idx LDGs in flight, then 8
// independent 8B table gathers in flight, then strided stores.
__global__ __launch_bounds__(256) void composite_kernel(
        const int* __restrict__ idx,
        float* __restrict__ out,
        int n_pix, int K) {
    const uint2* __restrict__ tab = g_tab;

    long warp_global = ((long)blockIdx.x * blockDim.x + threadIdx.x) >> 5;
    int lane = threadIdx.x & 31;
    long base = warp_global * (32 * PX_PER_THREAD) + lane;

    int ids[PX_PER_THREAD];
#pragma unroll
    for (int j = 0; j < PX_PER_THREAD; j++) {
        long p = base + 32 * j;
        ids[j] = (p < n_pix) ? __ldg(&idx[p * (long)K]) : -1;
    }

    // white in packed-fp16 form: half2(1,1), half2(1,0)
    const unsigned int ONE2 = 0x3C003C00u;
    const unsigned int ONE0 = 0x00003C00u;

    uint2 v[PX_PER_THREAD];
#pragma unroll
    for (int j = 0; j < PX_PER_THREAD; j++) {
        v[j] = (ids[j] >= 0) ? __ldg(&tab[ids[j]]) : make_uint2(ONE2, ONE0);
    }

#pragma unroll
    for (int j = 0; j < PX_PER_THREAD; j++) {
        long p = base + 32 * j;
        if (p < n_pix) {
            float2 rg = __half22float2(*(__half2*)&v[j].x);
            float2 b0 = __half22float2(*(__half2*)&v[j].y);
            out[p * 3 + 0] = rg.x;
            out[p * 3 + 1] = rg.y;
            out[p * 3 + 2] = b0.x;
        }
    }
}

extern "C" void kernel_launch(void* const* d_in, const int* in_sizes, int n_in,
                              void* d_out, int out_size) {
    const int*   idx       = (const int*)d_in[0];
    const float* features  = (const float*)d_in[1];
    const float* normals   = (const float*)d_in[2];
    const float* light_dir = (const float*)d_in[3];

    int n_pix = out_size / 3;                 // N*H*W
    int K     = in_sizes[0] / n_pix;          // fragments per pixel (10)
    int P     = in_sizes[1] / 3;              // number of points (100000)
    if (P > MAX_P) P = MAX_P;

    {
        int threads = 256;
        int blocks = (P + threads - 1) / threads;
        shade_kernel<<<blocks, threads>>>(features, normals, light_dir, P);
    }
    {
        int threads = 256;
        long px_per_block = (long)threads * PX_PER_THREAD;
        int blocks = (int)((n_pix + px_per_block - 1) / px_per_block);
        composite_kernel<<<blocks, threads>>>(idx, (float*)d_out, n_pix, K);
    }
}